// round 3
// baseline (speedup 1.0000x reference)
#include <cuda_runtime.h>
#include <math.h>
#include <float.h>

#define N_NODES 50000
#define N_EDGES 600000
#define N_GRAPHS 512
#define HID 128
#define LAT 64
#define NL 4
#define NSLOT 10

// ---------------- scratch (device globals; no allocation APIs) ----------------
__device__ float g_x[N_NODES * HID];            // current node features / JK output
__device__ float g_h[N_NODES * HID];            // GEMM input buffer
__device__ float g_t[N_NODES * HID];            // GEMM output buffer
__device__ float g_hs[NL][N_NODES * HID];       // per-layer hidden states (JK)
__device__ int   g_deg[N_NODES];
__device__ int   g_ptr[N_NODES + 1];
__device__ int   g_cursor[N_NODES];
__device__ int   g_srclist[N_EDGES];
__device__ float g_sum[NSLOT * HID];
__device__ float g_sumsq[NSLOT * HID];
__device__ float g_scale[NSLOT * HID];
__device__ float g_shift[NSLOT * HID];
__device__ float g_psum[N_GRAPHS * HID];
__device__ float g_pmax[N_GRAPHS * HID];
__device__ int   g_pcnt[N_GRAPHS];

__device__ __forceinline__ float gelu_exact(float x) {
    return 0.5f * x * (1.0f + erff(x * 0.70710678118654752f));
}

__device__ __forceinline__ void atomicMaxF(float* addr, float v) {
    if (__float_as_int(v) >= 0) {
        atomicMax((int*)addr, __float_as_int(v));
    } else {
        atomicMin((unsigned int*)addr, __float_as_uint(v));
    }
}

// ---------------- init ----------------
__global__ void zero_init_kernel() {
    int i = blockIdx.x * blockDim.x + threadIdx.x;
    if (i < NSLOT * HID) { g_sum[i] = 0.f; g_sumsq[i] = 0.f; }
    if (i < N_NODES) g_deg[i] = 0;
}

// ---------------- BatchNorm machinery ----------------
__global__ void colstats_kernel(const float* __restrict__ A, int M, int slot) {
    int c = threadIdx.x;                  // 128 threads = one column each
    float s = 0.f, s2 = 0.f;
    for (int n = blockIdx.x; n < M; n += gridDim.x) {
        float v = A[n * HID + c];
        s += v; s2 += v * v;
    }
    atomicAdd(&g_sum[slot * HID + c], s);
    atomicAdd(&g_sumsq[slot * HID + c], s2);
}

__global__ void bn_finalize_kernel(int slot, const float* __restrict__ gamma,
                                   const float* __restrict__ beta, float invN) {
    int c = threadIdx.x;
    float mean = g_sum[slot * HID + c] * invN;
    float var  = g_sumsq[slot * HID + c] * invN - mean * mean;
    float rstd = rsqrtf(var + 1e-5f);
    float sc = gamma[c] * rstd;
    g_scale[slot * HID + c] = sc;
    g_shift[slot * HID + c] = beta[c] - mean * sc;
}

template <bool GELU>
__global__ void bn_apply_kernel(const float* __restrict__ in, float* __restrict__ out, int slot) {
    int idx = blockIdx.x * blockDim.x + threadIdx.x;   // float4 index
    int c4 = idx & 31;                                 // column group (HID/4 = 32)
    float4 v  = ((const float4*)in)[idx];
    float4 sc = ((const float4*)(g_scale + slot * HID))[c4];
    float4 sh = ((const float4*)(g_shift + slot * HID))[c4];
    v.x = v.x * sc.x + sh.x;
    v.y = v.y * sc.y + sh.y;
    v.z = v.z * sc.z + sh.z;
    v.w = v.w * sc.w + sh.w;
    if (GELU) {
        v.x = gelu_exact(v.x); v.y = gelu_exact(v.y);
        v.z = gelu_exact(v.z); v.w = gelu_exact(v.w);
    }
    ((float4*)out)[idx] = v;
}

// ---------------- CSR build ----------------
__global__ void hist_kernel(const int* __restrict__ dst) {
    int i = blockIdx.x * blockDim.x + threadIdx.x;
    if (i < N_EDGES) atomicAdd(&g_deg[dst[i]], 1);
}

__global__ void scan_kernel() {
    __shared__ int s[1024];
    int tid = threadIdx.x;
    int off = 0;
    for (int base = 0; base < N_NODES; base += 1024) {
        int i = base + tid;
        int v = (i < N_NODES) ? g_deg[i] : 0;
        s[tid] = v;
        __syncthreads();
        for (int d = 1; d < 1024; d <<= 1) {
            int t = (tid >= d) ? s[tid - d] : 0;
            __syncthreads();
            s[tid] += t;
            __syncthreads();
        }
        int excl = s[tid] - v;
        if (i < N_NODES) { g_ptr[i] = off + excl; g_cursor[i] = off + excl; }
        int total = s[1023];
        __syncthreads();
        off += total;
    }
    if (tid == 0) g_ptr[N_NODES] = off;
}

__global__ void scatter_kernel(const int* __restrict__ src, const int* __restrict__ dst) {
    int i = blockIdx.x * blockDim.x + threadIdx.x;
    if (i < N_EDGES) {
        int pos = atomicAdd(&g_cursor[dst[i]], 1);
        g_srclist[pos] = src[i];
    }
}

// ---------------- GIN aggregation: h = (1+eps)*x + sum_{j->i} x_j ----------------
__global__ void agg_kernel(int l, const float* __restrict__ eps) {
    const float* __restrict__ in = (l == 0) ? g_x : g_hs[l - 1];
    int n = blockIdx.x;
    int c = threadIdx.x;
    float ev = __ldg(&eps[l]);
    float acc = (1.0f + ev) * in[n * HID + c];
    int b = g_ptr[n], e = g_ptr[n + 1];
    int j = b;
    for (; j + 1 < e; j += 2) {
        int s0 = g_srclist[j];
        int s1 = g_srclist[j + 1];
        acc += __ldg(&in[s0 * HID + c]);
        acc += __ldg(&in[s1 * HID + c]);
    }
    if (j < e) acc += __ldg(&in[g_srclist[j] * HID + c]);
    g_h[n * HID + c] = acc;
}

// ---------------- GEMM: C[M,128] = A[M,128] @ W[128,128] + bias ----------------
// Block: 256 threads, tile 128(M) x 128(N), thread tile 8x8 (split 4+4 rows/cols).
#define SA_STRIDE 132
#define GEMM_SMEM ((128 * SA_STRIDE + 128 * 128) * 4)

__global__ void __launch_bounds__(256, 1)
gemm_bias_kernel(const float* __restrict__ A, const float* __restrict__ W,
                 const float* __restrict__ bias, float* __restrict__ C, int M) {
    extern __shared__ float smem[];
    float* sA = smem;                      // [k][m] transposed, stride 132
    float* sB = smem + 128 * SA_STRIDE;    // [k][n], stride 128

    int tid = threadIdx.x;
    int m0 = blockIdx.x * 128;

    // load W (full 128x128) as float4, coalesced + conflict-free
    const float4* W4 = (const float4*)W;
    float4* sB4 = (float4*)sB;
#pragma unroll
    for (int i = 0; i < 16; i++) sB4[tid + i * 256] = W4[tid + i * 256];

    // load A tile transposed (guarded)
#pragma unroll
    for (int i = 0; i < 64; i++) {
        int idx = tid + i * 256;
        int m = idx >> 7, k = idx & 127;
        int gr = m0 + m;
        float v = (gr < M) ? A[gr * HID + k] : 0.0f;
        sA[k * SA_STRIDE + m] = v;
    }
    __syncthreads();

    int tx4 = (tid & 15) * 4;
    int ty4 = (tid >> 4) * 4;

    float acc[8][8];
#pragma unroll
    for (int i = 0; i < 8; i++)
#pragma unroll
        for (int j = 0; j < 8; j++) acc[i][j] = 0.0f;

#pragma unroll 8
    for (int k = 0; k < 128; k++) {
        float4 a0 = *(const float4*)(sA + k * SA_STRIDE + ty4);
        float4 a1 = *(const float4*)(sA + k * SA_STRIDE + 64 + ty4);
        float4 b0 = *(const float4*)(sB + k * 128 + tx4);
        float4 b1 = *(const float4*)(sB + k * 128 + 64 + tx4);
        float ar[8] = {a0.x, a0.y, a0.z, a0.w, a1.x, a1.y, a1.z, a1.w};
        float br[8] = {b0.x, b0.y, b0.z, b0.w, b1.x, b1.y, b1.z, b1.w};
#pragma unroll
        for (int i = 0; i < 8; i++)
#pragma unroll
            for (int j = 0; j < 8; j++) acc[i][j] += ar[i] * br[j];
    }

    float4 bb0 = *(const float4*)(bias + tx4);
    float4 bb1 = *(const float4*)(bias + 64 + tx4);
    float bs[8] = {bb0.x, bb0.y, bb0.z, bb0.w, bb1.x, bb1.y, bb1.z, bb1.w};

#pragma unroll
    for (int i = 0; i < 8; i++) {
        int r = (i < 4) ? (ty4 + i) : (64 + ty4 + i - 4);
        int gr = m0 + r;
        if (gr < M) {
            float4 o0 = make_float4(acc[i][0] + bs[0], acc[i][1] + bs[1],
                                    acc[i][2] + bs[2], acc[i][3] + bs[3]);
            float4 o1 = make_float4(acc[i][4] + bs[4], acc[i][5] + bs[5],
                                    acc[i][6] + bs[6], acc[i][7] + bs[7]);
            *(float4*)(C + gr * HID + tx4) = o0;
            *(float4*)(C + gr * HID + 64 + tx4) = o1;
        }
    }
}

// ---------------- JumpingKnowledge attention (warp per node) ----------------
__global__ void jk_kernel(const float* __restrict__ att) {
    int gw = (blockIdx.x * blockDim.x + threadIdx.x) >> 5;
    int lane = threadIdx.x & 31;
    if (gw >= N_NODES) return;

    float v[NL][4];
    float s[NL];
#pragma unroll
    for (int l = 0; l < NL; l++) {
        float d = 0.f;
#pragma unroll
        for (int j = 0; j < 4; j++) {
            int c = lane + 32 * j;
            v[l][j] = g_hs[l][gw * HID + c];
            d += v[l][j] * __ldg(&att[l * HID + c]);
        }
        s[l] = d;
    }
#pragma unroll
    for (int off = 16; off; off >>= 1) {
#pragma unroll
        for (int l = 0; l < NL; l++) s[l] += __shfl_xor_sync(0xffffffffu, s[l], off);
    }
    float m = fmaxf(fmaxf(s[0], s[1]), fmaxf(s[2], s[3]));
    float e[NL], tot = 0.f;
#pragma unroll
    for (int l = 0; l < NL; l++) { e[l] = expf((s[l] - m) * (1.0f / HID)); tot += e[l]; }
    float inv = 1.0f / tot;
#pragma unroll
    for (int j = 0; j < 4; j++) {
        float o = 0.f;
#pragma unroll
        for (int l = 0; l < NL; l++) o += e[l] * v[l][j];
        g_x[gw * HID + lane + 32 * j] = o * inv;
    }
}

// ---------------- pooling ----------------
__global__ void pool_init_kernel() {
    int i = blockIdx.x * blockDim.x + threadIdx.x;
    if (i < N_GRAPHS * HID) { g_psum[i] = 0.f; g_pmax[i] = -FLT_MAX; }
    if (i < N_GRAPHS) g_pcnt[i] = 0;
}

#define POOL_BLOCKS 100
__global__ void pool_scan_kernel(const int* __restrict__ batch) {
    const int CH = (N_NODES + POOL_BLOCKS - 1) / POOL_BLOCKS;   // 500
    int c = threadIdx.x;
    int n0 = blockIdx.x * CH;
    int n1 = min(n0 + CH, N_NODES);
    if (n0 >= n1) return;
    int g = batch[n0];
    float s = 0.f, mx = -FLT_MAX;
    int cnt = 0;
    for (int n = n0; n < n1; ++n) {
        int gn = batch[n];
        if (gn != g) {
            atomicAdd(&g_psum[g * HID + c], s);
            atomicMaxF(&g_pmax[g * HID + c], mx);
            if (c == 0) atomicAdd(&g_pcnt[g], cnt);
            g = gn; s = 0.f; mx = -FLT_MAX; cnt = 0;
        }
        float v = g_x[n * HID + c];
        s += v; mx = fmaxf(mx, v); cnt++;
    }
    atomicAdd(&g_psum[g * HID + c], s);
    atomicMaxF(&g_pmax[g * HID + c], mx);
    if (c == 0) atomicAdd(&g_pcnt[g], cnt);
}

// ---------------- head: pooled combine, fcA, LN, gelu+res, fcB ----------------
__global__ void head_kernel(const float* __restrict__ pwraw,
                            const float* __restrict__ fcA_w, const float* __restrict__ fcA_b,
                            const float* __restrict__ ln_g, const float* __restrict__ ln_b,
                            const float* __restrict__ fcB_w, const float* __restrict__ fcB_b,
                            float* __restrict__ out) {
    __shared__ float sp[HID];
    __shared__ float sh[HID];
    __shared__ float red[HID];
    int g = blockIdx.x, c = threadIdx.x;

    float w0 = pwraw[0], w1 = pwraw[1], w2 = pwraw[2];
    float mw = fmaxf(w0, fmaxf(w1, w2));
    float e0 = expf(w0 - mw), e1 = expf(w1 - mw), e2 = expf(w2 - mw);
    float et = 1.0f / (e0 + e1 + e2);
    float pw0 = e0 * et, pw1 = e1 * et, pw2 = e2 * et;

    float cnt = (float)g_pcnt[g];
    float s = g_psum[g * HID + c];
    float mean = s / fmaxf(cnt, 1.0f);
    float mx = (cnt > 0.f) ? g_pmax[g * HID + c] : 0.0f;
    float pooled = s * pw0 + mean * pw1 + mx * pw2;
    sp[c] = pooled;
    __syncthreads();

    float acc = fcA_b[c];
#pragma unroll 8
    for (int k = 0; k < HID; k++) acc += sp[k] * fcA_w[k * HID + c];

    // LayerNorm over the 128-wide row
    red[c] = acc;
    __syncthreads();
    for (int st = 64; st > 0; st >>= 1) { if (c < st) red[c] += red[c + st]; __syncthreads(); }
    float mu = red[0] * (1.0f / HID);
    __syncthreads();
    float d = acc - mu;
    red[c] = d * d;
    __syncthreads();
    for (int st = 64; st > 0; st >>= 1) { if (c < st) red[c] += red[c + st]; __syncthreads(); }
    float var = red[0] * (1.0f / HID);
    float y = d * rsqrtf(var + 1e-5f) * ln_g[c] + ln_b[c];
    float h = gelu_exact(y) + pooled;
    sh[c] = h;
    __syncthreads();

    if (c < LAT) {
        float o = fcB_b[c];
#pragma unroll 8
        for (int k = 0; k < HID; k++) o += sh[k] * fcB_w[k * LAT + c];
        out[g * LAT + c] = o;
    }
}

// ---------------- launcher ----------------
extern "C" void kernel_launch(void* const* d_in, const int* in_sizes, int n_in,
                              void* d_out, int out_size) {
    const float* x      = (const float*)d_in[0];
    const int*   ei     = (const int*)d_in[1];
    const int*   batch  = (const int*)d_in[2];
    const float* ibn_g  = (const float*)d_in[3];
    const float* ibn_b  = (const float*)d_in[4];
    const float* eps    = (const float*)d_in[5];
    const float* fc1_w  = (const float*)d_in[6];
    const float* fc1_b  = (const float*)d_in[7];
    const float* bn1_g  = (const float*)d_in[8];
    const float* bn1_b  = (const float*)d_in[9];
    const float* fc2_w  = (const float*)d_in[10];
    const float* fc2_b  = (const float*)d_in[11];
    const float* bn_g   = (const float*)d_in[12];
    const float* bn_b   = (const float*)d_in[13];
    const float* att_w  = (const float*)d_in[14];
    const float* pool_w = (const float*)d_in[15];
    const float* fcA_w  = (const float*)d_in[16];
    const float* fcA_b  = (const float*)d_in[17];
    const float* ln_g   = (const float*)d_in[18];
    const float* ln_b   = (const float*)d_in[19];
    const float* fcB_w  = (const float*)d_in[20];
    const float* fcB_b  = (const float*)d_in[21];
    float* out = (float*)d_out;

    const int* srcp = ei;
    const int* dstp = ei + N_EDGES;

    cudaFuncSetAttribute(gemm_bias_kernel,
                         cudaFuncAttributeMaxDynamicSharedMemorySize, GEMM_SMEM);

    float *p_x, *p_h, *p_t, *p_hs;
    cudaGetSymbolAddress((void**)&p_x, g_x);
    cudaGetSymbolAddress((void**)&p_h, g_h);
    cudaGetSymbolAddress((void**)&p_t, g_t);
    cudaGetSymbolAddress((void**)&p_hs, g_hs);

    const int GEMM_GRID = (N_NODES + 127) / 128;        // 391
    const int EW_GRID   = (N_NODES * HID) / (256 * 4);  // 6250 float4 blocks

    // init + input BN
    zero_init_kernel<<<(N_NODES + 255) / 256, 256>>>();
    colstats_kernel<<<256, 128>>>(x, N_NODES, 0);
    bn_finalize_kernel<<<1, 128>>>(0, ibn_g, ibn_b, 1.0f / N_NODES);
    bn_apply_kernel<false><<<EW_GRID, 256>>>(x, p_x, 0);

    // CSR build (once; reused by all 4 layers)
    hist_kernel<<<(N_EDGES + 511) / 512, 512>>>(dstp);
    scan_kernel<<<1, 1024>>>();
    scatter_kernel<<<(N_EDGES + 511) / 512, 512>>>(srcp, dstp);

    for (int l = 0; l < NL; l++) {
        int s1 = 1 + 2 * l, s2 = 2 + 2 * l;
        agg_kernel<<<N_NODES, 128>>>(l, eps);
        gemm_bias_kernel<<<GEMM_GRID, 256, GEMM_SMEM>>>(p_h, fc1_w + l * HID * HID,
                                                        fc1_b + l * HID, p_t, N_NODES);
        colstats_kernel<<<256, 128>>>(p_t, N_NODES, s1);
        bn_finalize_kernel<<<1, 128>>>(s1, bn1_g + l * HID, bn1_b + l * HID, 1.0f / N_NODES);
        bn_apply_kernel<true><<<EW_GRID, 256>>>(p_t, p_h, s1);
        gemm_bias_kernel<<<GEMM_GRID, 256, GEMM_SMEM>>>(p_h, fc2_w + l * HID * HID,
                                                        fc2_b + l * HID, p_t, N_NODES);
        colstats_kernel<<<256, 128>>>(p_t, N_NODES, s2);
        bn_finalize_kernel<<<1, 128>>>(s2, bn_g + l * HID, bn_b + l * HID, 1.0f / N_NODES);
        bn_apply_kernel<true><<<EW_GRID, 256>>>(p_t, p_hs + (size_t)l * N_NODES * HID, s2);
    }

    jk_kernel<<<(N_NODES * 32) / 256, 256>>>(att_w);
    pool_init_kernel<<<(N_GRAPHS * HID + 255) / 256, 256>>>();
    pool_scan_kernel<<<POOL_BLOCKS, 128>>>(batch);
    head_kernel<<<N_GRAPHS, 128>>>(pool_w, fcA_w, fcA_b, ln_g, ln_b, fcB_w, fcB_b, out);
}

// round 5
// speedup vs baseline: 1.0060x; 1.0060x over previous
#include <cuda_runtime.h>
#include <cuda_bf16.h>
#include <math.h>
#include <float.h>
#include <stdint.h>

#define N_NODES 50000
#define N_EDGES 600000
#define N_GRAPHS 512
#define HID 128
#define LAT 64
#define NL 4
#define NSLOT 10

// ======================= scratch =======================
__device__ float g_x[N_NODES * HID];
__device__ float g_h[N_NODES * HID];
__device__ float g_t[N_NODES * HID];
__device__ float g_hs[NL][N_NODES * HID];
__device__ int   g_deg[N_NODES];
__device__ int   g_ptr[N_NODES + 1];
__device__ int   g_cursor[N_NODES];
__device__ int   g_srclist[N_EDGES];
__device__ float g_sum[NSLOT * HID];
__device__ float g_sumsq[NSLOT * HID];
__device__ float g_scale[NSLOT * HID];
__device__ float g_shift[NSLOT * HID];
__device__ float g_psum[N_GRAPHS * HID];
__device__ float g_pmax[N_GRAPHS * HID];
__device__ int   g_pcnt[N_GRAPHS];
// per weight: 32KB hi + 32KB lo, B^T layout [n][k] row-major bf16
__device__ unsigned char g_wsplit[8][65536];

__device__ __forceinline__ float gelu_exact(float x) {
    return 0.5f * x * (1.0f + erff(x * 0.70710678118654752f));
}
__device__ __forceinline__ void atomicMaxF(float* addr, float v) {
    if (__float_as_int(v) >= 0) atomicMax((int*)addr, __float_as_int(v));
    else atomicMin((unsigned int*)addr, __float_as_uint(v));
}
__device__ __forceinline__ uint32_t smem_u32(const void* p) {
    uint32_t a;
    asm("{ .reg .u64 t; cvta.to.shared.u64 t, %1; cvt.u32.u64 %0, t; }" : "=r"(a) : "l"(p));
    return a;
}

#define LDMATRIX_X4(r, addr) \
    asm volatile("ldmatrix.sync.aligned.m8n8.x4.shared.b16 {%0,%1,%2,%3}, [%4];" \
        : "=r"((r)[0]), "=r"((r)[1]), "=r"((r)[2]), "=r"((r)[3]) : "r"(addr))

#define MMA16816(c, a, b) \
    asm volatile("mma.sync.aligned.m16n8k16.row.col.f32.bf16.bf16.f32 " \
        "{%0,%1,%2,%3}, {%4,%5,%6,%7}, {%8,%9}, {%0,%1,%2,%3};" \
        : "+f"((c)[0]), "+f"((c)[1]), "+f"((c)[2]), "+f"((c)[3]) \
        : "r"((a)[0]), "r"((a)[1]), "r"((a)[2]), "r"((a)[3]), "r"((b)[0]), "r"((b)[1]))

// ======================= small kernels =======================
__global__ void zero_init_kernel() {
    int i = blockIdx.x * blockDim.x + threadIdx.x;
    if (i < NSLOT * HID) { g_sum[i] = 0.f; g_sumsq[i] = 0.f; }
    if (i < N_NODES) g_deg[i] = 0;
}

__global__ void colstats_kernel(const float* __restrict__ A, int M, int slot) {
    int c = threadIdx.x;
    float s = 0.f, s2 = 0.f;
    for (int n = blockIdx.x; n < M; n += gridDim.x) {
        float v = A[n * HID + c];
        s += v; s2 += v * v;
    }
    atomicAdd(&g_sum[slot * HID + c], s);
    atomicAdd(&g_sumsq[slot * HID + c], s2);
}

__global__ void bn_finalize_kernel(int slot, const float* __restrict__ gamma,
                                   const float* __restrict__ beta, float invN) {
    int c = threadIdx.x;
    float mean = g_sum[slot * HID + c] * invN;
    float var  = g_sumsq[slot * HID + c] * invN - mean * mean;
    float rstd = rsqrtf(var + 1e-5f);
    float sc = gamma[c] * rstd;
    g_scale[slot * HID + c] = sc;
    g_shift[slot * HID + c] = beta[c] - mean * sc;
}

template <bool GELU>
__global__ void bn_apply_kernel(const float* __restrict__ in, float* __restrict__ out, int slot) {
    int idx = blockIdx.x * blockDim.x + threadIdx.x;
    int c4 = idx & 31;
    float4 v  = ((const float4*)in)[idx];
    float4 sc = ((const float4*)(g_scale + slot * HID))[c4];
    float4 sh = ((const float4*)(g_shift + slot * HID))[c4];
    v.x = v.x * sc.x + sh.x; v.y = v.y * sc.y + sh.y;
    v.z = v.z * sc.z + sh.z; v.w = v.w * sc.w + sh.w;
    if (GELU) {
        v.x = gelu_exact(v.x); v.y = gelu_exact(v.y);
        v.z = gelu_exact(v.z); v.w = gelu_exact(v.w);
    }
    ((float4*)out)[idx] = v;
}

// ---------------- CSR build ----------------
__global__ void hist_kernel(const int* __restrict__ dst) {
    int i = blockIdx.x * blockDim.x + threadIdx.x;
    if (i < N_EDGES) atomicAdd(&g_deg[dst[i]], 1);
}

__global__ void scan_kernel() {
    __shared__ int s[1024];
    int tid = threadIdx.x;
    int off = 0;
    for (int base = 0; base < N_NODES; base += 1024) {
        int i = base + tid;
        int v = (i < N_NODES) ? g_deg[i] : 0;
        s[tid] = v;
        __syncthreads();
        for (int d = 1; d < 1024; d <<= 1) {
            int t = (tid >= d) ? s[tid - d] : 0;
            __syncthreads();
            s[tid] += t;
            __syncthreads();
        }
        int excl = s[tid] - v;
        if (i < N_NODES) { g_ptr[i] = off + excl; g_cursor[i] = off + excl; }
        int total = s[1023];
        __syncthreads();
        off += total;
    }
    if (tid == 0) g_ptr[N_NODES] = off;
}

__global__ void scatter_kernel(const int* __restrict__ src, const int* __restrict__ dst) {
    int i = blockIdx.x * blockDim.x + threadIdx.x;
    if (i < N_EDGES) {
        int pos = atomicAdd(&g_cursor[dst[i]], 1);
        g_srclist[pos] = src[i];
    }
}

// ---------------- GIN aggregation ----------------
__global__ void agg_kernel(int l, const float* __restrict__ eps) {
    const float* __restrict__ in = (l == 0) ? g_x : g_hs[l - 1];
    int n = blockIdx.x;
    int c = threadIdx.x;
    float ev = __ldg(&eps[l]);
    float acc = (1.0f + ev) * in[n * HID + c];
    int b = g_ptr[n], e = g_ptr[n + 1];
    int j = b;
    for (; j + 1 < e; j += 2) {
        int s0 = g_srclist[j];
        int s1 = g_srclist[j + 1];
        acc += __ldg(&in[s0 * HID + c]);
        acc += __ldg(&in[s1 * HID + c]);
    }
    if (j < e) acc += __ldg(&in[g_srclist[j] * HID + c]);
    g_h[n * HID + c] = acc;
}

// ---------------- weight split prep: B^T[n][k] hi/lo bf16 ----------------
__global__ void wsplit_kernel(const float* __restrict__ fc1_w, const float* __restrict__ fc2_w) {
    int w = blockIdx.x >> 3;              // 0..7
    int l = w >> 1, which = w & 1;
    const float* W = (which ? fc2_w : fc1_w) + l * HID * HID;
    __nv_bfloat16* bh = (__nv_bfloat16*)(g_wsplit[w]);
    __nv_bfloat16* bl = (__nv_bfloat16*)(g_wsplit[w] + 32768);
    int chunk = blockIdx.x & 7;
    for (int i = threadIdx.x + chunk * 2048; i < (chunk + 1) * 2048; i += 256) {
        int n = i >> 7, k = i & 127;       // Bt[n][k] = W[k][n]
        float v = W[k * HID + n];
        __nv_bfloat16 hi = __float2bfloat16_rn(v);
        float lof = v - __bfloat162float(hi);
        bh[n * 128 + k] = hi;
        bl[n * 128 + k] = __float2bfloat16_rn(lof);
    }
}

// ---------------- HMMA GEMM: C = A @ W + bias, bf16 3-term split ----------------
// smem layout: padded bf16 tiles, row stride 136 elems (272 B) for conflict-free ldmatrix
#define APAD 136
#define TILE_BYTES (128 * APAD * 2)     // 34816
#define SM_AH 0
#define SM_AL TILE_BYTES
#define SM_BH (2 * TILE_BYTES)
#define SM_BL (3 * TILE_BYTES)
#define TC_SMEM (4 * TILE_BYTES)        // 139264

template <int PRE>
__global__ void __launch_bounds__(256)
mma_gemm_kernel(const float* __restrict__ A, int widx, const float* __restrict__ bias,
                float* __restrict__ C, int M, int slot, int oslot) {
    extern __shared__ unsigned char smem[];
    int tid = threadIdx.x, lane = tid & 31, wid = tid >> 5;
    int m0 = blockIdx.x * 128;
    uint32_t sb = smem_u32(smem);

    // ---- B: copy pre-split B^T (hi+lo), inserting row padding ----
    {
        const uint4* srcH = (const uint4*)(g_wsplit[widx]);
        const uint4* srcL = (const uint4*)(g_wsplit[widx] + 32768);
        for (int i = tid; i < 2048; i += 256) {
            int n = i >> 4, s = i & 15;
            *(uint4*)(smem + SM_BH + n * (APAD * 2) + s * 16) = srcH[i];
            *(uint4*)(smem + SM_BL + n * (APAD * 2) + s * 16) = srcL[i];
        }
    }

    // ---- A: load, optional BN+GELU, split hi/lo, padded store ----
    {
        int r = tid >> 1;
        int half = (tid & 1) * 64;
        bool valid = (m0 + r) < M;
        const float4* Arow = (const float4*)(A + (size_t)(m0 + r) * HID + half);
#pragma unroll 4
        for (int jj = 0; jj < 16; jj++) {
            float4 v = valid ? __ldg(Arow + jj) : make_float4(0.f, 0.f, 0.f, 0.f);
            if (PRE) {
                float4 sc = __ldg((const float4*)(g_scale + slot * HID + half) + jj);
                float4 sh = __ldg((const float4*)(g_shift + slot * HID + half) + jj);
                v.x = gelu_exact(v.x * sc.x + sh.x);
                v.y = gelu_exact(v.y * sc.y + sh.y);
                v.z = gelu_exact(v.z * sc.z + sh.z);
                v.w = gelu_exact(v.w * sc.w + sh.w);
            }
            __nv_bfloat16 h0 = __float2bfloat16_rn(v.x), h1 = __float2bfloat16_rn(v.y);
            __nv_bfloat16 h2 = __float2bfloat16_rn(v.z), h3 = __float2bfloat16_rn(v.w);
            float l0 = v.x - __bfloat162float(h0), l1 = v.y - __bfloat162float(h1);
            float l2 = v.z - __bfloat162float(h2), l3 = v.w - __bfloat162float(h3);
            uint2 hp, lp;
            hp.x = (uint32_t)__bfloat16_as_ushort(h0) | ((uint32_t)__bfloat16_as_ushort(h1) << 16);
            hp.y = (uint32_t)__bfloat16_as_ushort(h2) | ((uint32_t)__bfloat16_as_ushort(h3) << 16);
            lp.x = (uint32_t)__bfloat16_as_ushort(__float2bfloat16_rn(l0)) |
                   ((uint32_t)__bfloat16_as_ushort(__float2bfloat16_rn(l1)) << 16);
            lp.y = (uint32_t)__bfloat16_as_ushort(__float2bfloat16_rn(l2)) |
                   ((uint32_t)__bfloat16_as_ushort(__float2bfloat16_rn(l3)) << 16);
            uint32_t off = r * (APAD * 2) + (half + jj * 4) * 2;
            *(uint2*)(smem + SM_AH + off) = hp;
            *(uint2*)(smem + SM_AL + off) = lp;
        }
    }
    __syncthreads();

    // ---- MMA mainloop: warp grid 4(M) x 2(N), warp tile 32x64 ----
    int wm = wid & 3, wn = wid >> 2;
    int mbase = wm * 32, nbase = wn * 64;
    float acc[2][8][4];
#pragma unroll
    for (int i = 0; i < 2; i++)
#pragma unroll
        for (int j = 0; j < 8; j++)
#pragma unroll
            for (int c = 0; c < 4; c++) acc[i][j][c] = 0.f;

    int q = lane >> 3, riq = lane & 7;
#pragma unroll
    for (int ks = 0; ks < 8; ks++) {
        uint32_t ah[2][4], al[2][4], bh[8][2], bl[8][2];
        // A fragments: x4 covers 16x16 (quadrants: row0-7/k0, row8-15/k0, row0-7/k8, row8-15/k8)
#pragma unroll
        for (int i = 0; i < 2; i++) {
            int row = mbase + i * 16 + (q & 1) * 8 + riq;
            int kb = ks * 16 + (q >> 1) * 8;
            uint32_t addr = sb + SM_AH + row * (APAD * 2) + kb * 2;
            LDMATRIX_X4(ah[i], addr);
            LDMATRIX_X4(al[i], addr + (SM_AL - SM_AH));
        }
        // B fragments: x4 covers 2 n-frags (quadrants: n0-7/k0, n0-7/k8, n8-15/k0, n8-15/k8)
#pragma unroll
        for (int j = 0; j < 4; j++) {
            int n = nbase + j * 16 + (q >> 1) * 8 + riq;
            int kb = ks * 16 + (q & 1) * 8;
            uint32_t addr = sb + SM_BH + n * (APAD * 2) + kb * 2;
            uint32_t t4[4];
            LDMATRIX_X4(t4, addr);
            bh[j * 2][0] = t4[0]; bh[j * 2][1] = t4[1];
            bh[j * 2 + 1][0] = t4[2]; bh[j * 2 + 1][1] = t4[3];
            LDMATRIX_X4(t4, addr + (SM_BL - SM_BH));
            bl[j * 2][0] = t4[0]; bl[j * 2][1] = t4[1];
            bl[j * 2 + 1][0] = t4[2]; bl[j * 2 + 1][1] = t4[3];
        }
#pragma unroll
        for (int i = 0; i < 2; i++)
#pragma unroll
            for (int j = 0; j < 8; j++) {
                MMA16816(acc[i][j], ah[i], bh[j]);
                MMA16816(acc[i][j], ah[i], bl[j]);
                MMA16816(acc[i][j], al[i], bh[j]);
            }
    }
    __syncthreads();   // done reading A/B tiles; reuse smem as C staging

    // ---- epilogue: regs -> smem staging (+bias) -> coalesced STG + fused stats ----
    float* sC = (float*)smem;   // 128 x 132 floats = 67584 B (fits in Ah+Al region)
    int g = lane >> 2, tc = (lane & 3) * 2;
#pragma unroll
    for (int i = 0; i < 2; i++) {
        int row0 = mbase + i * 16 + g;
#pragma unroll
        for (int j = 0; j < 8; j++) {
            int col = nbase + j * 8 + tc;
            float b0 = __ldg(&bias[col]), b1 = __ldg(&bias[col + 1]);
            sC[row0 * 132 + col]           = acc[i][j][0] + b0;
            sC[row0 * 132 + col + 1]       = acc[i][j][1] + b1;
            sC[(row0 + 8) * 132 + col]     = acc[i][j][2] + b0;
            sC[(row0 + 8) * 132 + col + 1] = acc[i][j][3] + b1;
        }
    }
    __syncthreads();

    {
        int r2 = tid >> 1, h = (tid & 1);
        if (m0 + r2 < M) {
            float4* dst = (float4*)(C + (size_t)(m0 + r2) * HID + h * 64);
            const float4* src = (const float4*)(sC + r2 * 132 + h * 64);
#pragma unroll
            for (int i = 0; i < 16; i++) dst[i] = src[i];
        }
    }

    {
        int nrows = min(128, M - m0);
        int c = tid & 127;
        int rbeg = (tid >> 7) * 64;
        int rend = min(rbeg + 64, nrows);
        float s = 0.f, s2 = 0.f;
        for (int rr = rbeg; rr < rend; rr++) {
            float v = sC[rr * 132 + c];
            s += v; s2 += v * v;
        }
        atomicAdd(&g_sum[oslot * HID + c], s);
        atomicAdd(&g_sumsq[oslot * HID + c], s2);
    }
}

// ---------------- JumpingKnowledge attention ----------------
__global__ void jk_kernel(const float* __restrict__ att) {
    int gw = (blockIdx.x * blockDim.x + threadIdx.x) >> 5;
    int lane = threadIdx.x & 31;
    if (gw >= N_NODES) return;
    float v[NL][4];
    float s[NL];
#pragma unroll
    for (int l = 0; l < NL; l++) {
        float d = 0.f;
#pragma unroll
        for (int j = 0; j < 4; j++) {
            int c = lane + 32 * j;
            v[l][j] = g_hs[l][gw * HID + c];
            d += v[l][j] * __ldg(&att[l * HID + c]);
        }
        s[l] = d;
    }
#pragma unroll
    for (int off = 16; off; off >>= 1) {
#pragma unroll
        for (int l = 0; l < NL; l++) s[l] += __shfl_xor_sync(0xffffffffu, s[l], off);
    }
    float m = fmaxf(fmaxf(s[0], s[1]), fmaxf(s[2], s[3]));
    float e[NL], tot = 0.f;
#pragma unroll
    for (int l = 0; l < NL; l++) { e[l] = expf((s[l] - m) * (1.0f / HID)); tot += e[l]; }
    float inv = 1.0f / tot;
#pragma unroll
    for (int j = 0; j < 4; j++) {
        float o = 0.f;
#pragma unroll
        for (int l = 0; l < NL; l++) o += e[l] * v[l][j];
        g_x[gw * HID + lane + 32 * j] = o * inv;
    }
}

// ---------------- pooling ----------------
__global__ void pool_init_kernel() {
    int i = blockIdx.x * blockDim.x + threadIdx.x;
    if (i < N_GRAPHS * HID) { g_psum[i] = 0.f; g_pmax[i] = -FLT_MAX; }
    if (i < N_GRAPHS) g_pcnt[i] = 0;
}

#define POOL_BLOCKS 100
__global__ void pool_scan_kernel(const int* __restrict__ batch) {
    const int CH = (N_NODES + POOL_BLOCKS - 1) / POOL_BLOCKS;
    int c = threadIdx.x;
    int n0 = blockIdx.x * CH;
    int n1 = min(n0 + CH, N_NODES);
    if (n0 >= n1) return;
    int g = batch[n0];
    float s = 0.f, mx = -FLT_MAX;
    int cnt = 0;
    for (int n = n0; n < n1; ++n) {
        int gn = batch[n];
        if (gn != g) {
            atomicAdd(&g_psum[g * HID + c], s);
            atomicMaxF(&g_pmax[g * HID + c], mx);
            if (c == 0) atomicAdd(&g_pcnt[g], cnt);
            g = gn; s = 0.f; mx = -FLT_MAX; cnt = 0;
        }
        float v = g_x[n * HID + c];
        s += v; mx = fmaxf(mx, v); cnt++;
    }
    atomicAdd(&g_psum[g * HID + c], s);
    atomicMaxF(&g_pmax[g * HID + c], mx);
    if (c == 0) atomicAdd(&g_pcnt[g], cnt);
}

// ---------------- head ----------------
__global__ void head_kernel(const float* __restrict__ pwraw,
                            const float* __restrict__ fcA_w, const float* __restrict__ fcA_b,
                            const float* __restrict__ ln_g, const float* __restrict__ ln_b,
                            const float* __restrict__ fcB_w, const float* __restrict__ fcB_b,
                            float* __restrict__ out) {
    __shared__ float sp[HID];
    __shared__ float sh[HID];
    __shared__ float red[HID];
    int g = blockIdx.x, c = threadIdx.x;

    float w0 = pwraw[0], w1 = pwraw[1], w2 = pwraw[2];
    float mw = fmaxf(w0, fmaxf(w1, w2));
    float e0 = expf(w0 - mw), e1 = expf(w1 - mw), e2 = expf(w2 - mw);
    float et = 1.0f / (e0 + e1 + e2);
    float pw0 = e0 * et, pw1 = e1 * et, pw2 = e2 * et;

    float cnt = (float)g_pcnt[g];
    float s = g_psum[g * HID + c];
    float mean = s / fmaxf(cnt, 1.0f);
    float mx = (cnt > 0.f) ? g_pmax[g * HID + c] : 0.0f;
    float pooled = s * pw0 + mean * pw1 + mx * pw2;
    sp[c] = pooled;
    __syncthreads();

    float acc = fcA_b[c];
#pragma unroll 8
    for (int k = 0; k < HID; k++) acc += sp[k] * fcA_w[k * HID + c];

    red[c] = acc;
    __syncthreads();
    for (int st = 64; st > 0; st >>= 1) { if (c < st) red[c] += red[c + st]; __syncthreads(); }
    float mu = red[0] * (1.0f / HID);
    __syncthreads();
    float d = acc - mu;
    red[c] = d * d;
    __syncthreads();
    for (int st = 64; st > 0; st >>= 1) { if (c < st) red[c] += red[c + st]; __syncthreads(); }
    float var = red[0] * (1.0f / HID);
    float y = d * rsqrtf(var + 1e-5f) * ln_g[c] + ln_b[c];
    float h = gelu_exact(y) + pooled;
    sh[c] = h;
    __syncthreads();

    if (c < LAT) {
        float o = fcB_b[c];
#pragma unroll 8
        for (int k = 0; k < HID; k++) o += sh[k] * fcB_w[k * LAT + c];
        out[g * LAT + c] = o;
    }
}

// ---------------- launcher ----------------
extern "C" void kernel_launch(void* const* d_in, const int* in_sizes, int n_in,
                              void* d_out, int out_size) {
    const float* x      = (const float*)d_in[0];
    const int*   ei     = (const int*)d_in[1];
    const int*   batch  = (const int*)d_in[2];
    const float* ibn_g  = (const float*)d_in[3];
    const float* ibn_b  = (const float*)d_in[4];
    const float* eps    = (const float*)d_in[5];
    const float* fc1_w  = (const float*)d_in[6];
    const float* fc1_b  = (const float*)d_in[7];
    const float* bn1_g  = (const float*)d_in[8];
    const float* bn1_b  = (const float*)d_in[9];
    const float* fc2_w  = (const float*)d_in[10];
    const float* fc2_b  = (const float*)d_in[11];
    const float* bn_g   = (const float*)d_in[12];
    const float* bn_b   = (const float*)d_in[13];
    const float* att_w  = (const float*)d_in[14];
    const float* pool_w = (const float*)d_in[15];
    const float* fcA_w  = (const float*)d_in[16];
    const float* fcA_b  = (const float*)d_in[17];
    const float* ln_g   = (const float*)d_in[18];
    const float* ln_b   = (const float*)d_in[19];
    const float* fcB_w  = (const float*)d_in[20];
    const float* fcB_b  = (const float*)d_in[21];
    float* out = (float*)d_out;

    const int* srcp = ei;
    const int* dstp = ei + N_EDGES;

    cudaFuncSetAttribute(mma_gemm_kernel<0>, cudaFuncAttributeMaxDynamicSharedMemorySize, TC_SMEM);
    cudaFuncSetAttribute(mma_gemm_kernel<1>, cudaFuncAttributeMaxDynamicSharedMemorySize, TC_SMEM);

    float *p_x, *p_h, *p_t, *p_hs;
    cudaGetSymbolAddress((void**)&p_x, g_x);
    cudaGetSymbolAddress((void**)&p_h, g_h);
    cudaGetSymbolAddress((void**)&p_t, g_t);
    cudaGetSymbolAddress((void**)&p_hs, g_hs);

    const int GEMM_GRID = (N_NODES + 127) / 128;        // 391
    const int EW_GRID   = (N_NODES * HID) / (256 * 4);  // 6250

    // init + weight split + input BN
    zero_init_kernel<<<(N_NODES + 255) / 256, 256>>>();
    wsplit_kernel<<<64, 256>>>(fc1_w, fc2_w);
    colstats_kernel<<<256, 128>>>(x, N_NODES, 0);
    bn_finalize_kernel<<<1, 128>>>(0, ibn_g, ibn_b, 1.0f / N_NODES);
    bn_apply_kernel<false><<<EW_GRID, 256>>>(x, p_x, 0);

    // CSR build (reused by all layers)
    hist_kernel<<<(N_EDGES + 511) / 512, 512>>>(dstp);
    scan_kernel<<<1, 1024>>>();
    scatter_kernel<<<(N_EDGES + 511) / 512, 512>>>(srcp, dstp);

    for (int l = 0; l < NL; l++) {
        int s1 = 1 + 2 * l, s2 = 2 + 2 * l;
        agg_kernel<<<N_NODES, 128>>>(l, eps);
        // GEMM1: raw A, fused stats into slot s1
        mma_gemm_kernel<0><<<GEMM_GRID, 256, TC_SMEM>>>(p_h, l * 2 + 0, fc1_b + l * HID,
                                                        p_t, N_NODES, 0, s1);
        bn_finalize_kernel<<<1, 128>>>(s1, bn1_g + l * HID, bn1_b + l * HID, 1.0f / N_NODES);
        // GEMM2: fused BN(s1)+GELU on A load, in-place, fused stats into s2
        mma_gemm_kernel<1><<<GEMM_GRID, 256, TC_SMEM>>>(p_t, l * 2 + 1, fc2_b + l * HID,
                                                        p_t, N_NODES, s1, s2);
        bn_finalize_kernel<<<1, 128>>>(s2, bn_g + l * HID, bn_b + l * HID, 1.0f / N_NODES);
        bn_apply_kernel<true><<<EW_GRID, 256>>>(p_t, p_hs + (size_t)l * N_NODES * HID, s2);
    }

    jk_kernel<<<(N_NODES * 32) / 256, 256>>>(att_w);
    pool_init_kernel<<<(N_GRAPHS * HID + 255) / 256, 256>>>();
    pool_scan_kernel<<<POOL_BLOCKS, 128>>>(batch);
    head_kernel<<<N_GRAPHS, 128>>>(pool_w, fcA_w, fcA_b, ln_g, ln_b, fcB_w, fcB_b, out);
}

// round 7
// speedup vs baseline: 1.8032x; 1.7925x over previous
#include <cuda_runtime.h>
#include <cuda_bf16.h>
#include <math.h>
#include <float.h>
#include <stdint.h>

#define N_NODES 50000
#define N_EDGES 600000
#define N_GRAPHS 512
#define HID 128
#define LAT 64
#define NL 4
#define NSLOT 10

// ======================= scratch =======================
__device__ float g_x[N_NODES * HID];
__device__ float g_h[N_NODES * HID];
__device__ float g_t[N_NODES * HID];
__device__ float g_hs[NL][N_NODES * HID];
__device__ int   g_deg[N_NODES];
__device__ int   g_ptr[N_NODES + 1];
__device__ int   g_cursor[N_NODES];
__device__ int   g_srclist[N_EDGES];
__device__ int   g_bsum[64];
__device__ int   g_boff[64];
__device__ float g_sum[NSLOT * HID];
__device__ float g_sumsq[NSLOT * HID];
__device__ float g_psum[N_GRAPHS * HID];
__device__ float g_pmax[N_GRAPHS * HID];
__device__ int   g_pcnt[N_GRAPHS];
// per weight: 32KB hi + 32KB lo, B^T layout [n][k] row-major bf16
__device__ unsigned char g_wsplit[8][65536];

__device__ __forceinline__ float gelu_exact(float x) {
    return 0.5f * x * (1.0f + erff(x * 0.70710678118654752f));
}
__device__ __forceinline__ void atomicMaxF(float* addr, float v) {
    if (__float_as_int(v) >= 0) atomicMax((int*)addr, __float_as_int(v));
    else atomicMin((unsigned int*)addr, __float_as_uint(v));
}
__device__ __forceinline__ uint32_t smem_u32(const void* p) {
    uint32_t a;
    asm("{ .reg .u64 t; cvta.to.shared.u64 t, %1; cvt.u32.u64 %0, t; }" : "=r"(a) : "l"(p));
    return a;
}

#define LDMATRIX_X4(r, addr) \
    asm volatile("ldmatrix.sync.aligned.m8n8.x4.shared.b16 {%0,%1,%2,%3}, [%4];" \
        : "=r"((r)[0]), "=r"((r)[1]), "=r"((r)[2]), "=r"((r)[3]) : "r"(addr))

#define MMA16816(c, a, b) \
    asm volatile("mma.sync.aligned.m16n8k16.row.col.f32.bf16.bf16.f32 " \
        "{%0,%1,%2,%3}, {%4,%5,%6,%7}, {%8,%9}, {%0,%1,%2,%3};" \
        : "+f"((c)[0]), "+f"((c)[1]), "+f"((c)[2]), "+f"((c)[3]) \
        : "r"((a)[0]), "r"((a)[1]), "r"((a)[2]), "r"((a)[3]), "r"((b)[0]), "r"((b)[1]))

// finalize BN stats for `slot` into smem scale/shift (first 128 threads)
__device__ __forceinline__ void finalize_to_smem(int slot, const float* gamma,
                                                 const float* beta,
                                                 float* sScale, float* sShift, int tid) {
    if (tid < HID) {
        const float invN = 1.0f / N_NODES;
        float mean = g_sum[slot * HID + tid] * invN;
        float var  = g_sumsq[slot * HID + tid] * invN - mean * mean;
        float sc = __ldg(&gamma[tid]) * rsqrtf(var + 1e-5f);
        sScale[tid] = sc;
        sShift[tid] = __ldg(&beta[tid]) - mean * sc;
    }
}

// ======================= init (also pool init) =======================
// NOTE: grid MUST cover N_GRAPHS*HID = 65536 (R6 bug: only covered N_NODES,
// leaving g_psum/g_pmax tails un-reset across graph replays -> divergence).
__global__ void zero_init_kernel() {
    int i = blockIdx.x * blockDim.x + threadIdx.x;
    if (i < NSLOT * HID) { g_sum[i] = 0.f; g_sumsq[i] = 0.f; }
    if (i < N_NODES) g_deg[i] = 0;
    if (i < N_GRAPHS * HID) { g_psum[i] = 0.f; g_pmax[i] = -FLT_MAX; }
    if (i < N_GRAPHS) g_pcnt[i] = 0;
}

__global__ void colstats_kernel(const float* __restrict__ A, int M, int slot) {
    int c = threadIdx.x;
    float s = 0.f, s2 = 0.f;
    for (int n = blockIdx.x; n < M; n += gridDim.x) {
        float v = A[n * HID + c];
        s += v; s2 += v * v;
    }
    atomicAdd(&g_sum[slot * HID + c], s);
    atomicAdd(&g_sumsq[slot * HID + c], s2);
}

// BN apply with inlined finalize
template <bool GELU>
__global__ void bn_apply_kernel(const float* __restrict__ in, float* __restrict__ out,
                                int slot, const float* __restrict__ gamma,
                                const float* __restrict__ beta) {
    __shared__ float sScale[HID], sShift[HID];
    int tid = threadIdx.x;
    finalize_to_smem(slot, gamma, beta, sScale, sShift, tid);
    __syncthreads();
    int idx = blockIdx.x * blockDim.x + tid;
    int c4 = idx & 31;
    float4 v  = ((const float4*)in)[idx];
    float4 sc = ((const float4*)sScale)[c4];
    float4 sh = ((const float4*)sShift)[c4];
    v.x = v.x * sc.x + sh.x; v.y = v.y * sc.y + sh.y;
    v.z = v.z * sc.z + sh.z; v.w = v.w * sc.w + sh.w;
    if (GELU) {
        v.x = gelu_exact(v.x); v.y = gelu_exact(v.y);
        v.z = gelu_exact(v.z); v.w = gelu_exact(v.w);
    }
    ((float4*)out)[idx] = v;
}

// ---------------- CSR build ----------------
__global__ void hist_kernel(const int* __restrict__ dst) {
    int i = blockIdx.x * blockDim.x + threadIdx.x;
    if (i < N_EDGES) atomicAdd(&g_deg[dst[i]], 1);
}

// 3-phase parallel scan over degrees
__global__ void scan1_kernel() {     // grid 49, block 1024: per-block inclusive scan
    __shared__ int s[1024];
    int tid = threadIdx.x;
    int i = blockIdx.x * 1024 + tid;
    int v = (i < N_NODES) ? g_deg[i] : 0;
    s[tid] = v;
    __syncthreads();
#pragma unroll
    for (int d = 1; d < 1024; d <<= 1) {
        int t = (tid >= d) ? s[tid - d] : 0;
        __syncthreads();
        s[tid] += t;
        __syncthreads();
    }
    if (i < N_NODES) g_cursor[i] = s[tid];          // temp: inclusive within block
    if (tid == 1023) g_bsum[blockIdx.x] = s[tid];
}

__global__ void scan2_kernel(int nblk) {             // 1 block, 64 threads
    __shared__ int s[64];
    int tid = threadIdx.x;
    int v = (tid < nblk) ? g_bsum[tid] : 0;
    s[tid] = v;
    __syncthreads();
#pragma unroll
    for (int d = 1; d < 64; d <<= 1) {
        int t = (tid >= d) ? s[tid - d] : 0;
        __syncthreads();
        s[tid] += t;
        __syncthreads();
    }
    if (tid < nblk) g_boff[tid] = s[tid] - v;        // exclusive block offset
}

__global__ void scan3_kernel() {                     // finalize ptr + cursor
    int i = blockIdx.x * 1024 + threadIdx.x;
    if (i < N_NODES) {
        int p = g_boff[blockIdx.x] + g_cursor[i] - g_deg[i];
        g_ptr[i] = p;
        g_cursor[i] = p;
    }
    if (i == 0) g_ptr[N_NODES] = N_EDGES;
}

__global__ void scatter_kernel(const int* __restrict__ src, const int* __restrict__ dst) {
    int i = blockIdx.x * blockDim.x + threadIdx.x;
    if (i < N_EDGES) {
        int pos = atomicAdd(&g_cursor[dst[i]], 1);
        g_srclist[pos] = src[i];
    }
}

// ---------------- GIN aggregation ----------------
__global__ void agg_kernel(int l, const float* __restrict__ eps) {
    const float* __restrict__ in = (l == 0) ? g_x : g_hs[l - 1];
    int n = blockIdx.x;
    int c = threadIdx.x;
    float ev = __ldg(&eps[l]);
    float acc = (1.0f + ev) * in[n * HID + c];
    int b = g_ptr[n], e = g_ptr[n + 1];
    int j = b;
    for (; j + 3 < e; j += 4) {
        int s0 = g_srclist[j], s1 = g_srclist[j + 1];
        int s2 = g_srclist[j + 2], s3 = g_srclist[j + 3];
        float v0 = __ldg(&in[s0 * HID + c]);
        float v1 = __ldg(&in[s1 * HID + c]);
        float v2 = __ldg(&in[s2 * HID + c]);
        float v3 = __ldg(&in[s3 * HID + c]);
        acc += (v0 + v1) + (v2 + v3);
    }
    for (; j < e; j++) acc += __ldg(&in[g_srclist[j] * HID + c]);
    g_h[n * HID + c] = acc;
}

// ---------------- weight split prep: B^T[n][k] hi/lo bf16 ----------------
__global__ void wsplit_kernel(const float* __restrict__ fc1_w, const float* __restrict__ fc2_w) {
    int w = blockIdx.x >> 3;
    int l = w >> 1, which = w & 1;
    const float* W = (which ? fc2_w : fc1_w) + l * HID * HID;
    __nv_bfloat16* bh = (__nv_bfloat16*)(g_wsplit[w]);
    __nv_bfloat16* bl = (__nv_bfloat16*)(g_wsplit[w] + 32768);
    int chunk = blockIdx.x & 7;
    for (int i = threadIdx.x + chunk * 2048; i < (chunk + 1) * 2048; i += 256) {
        int n = i >> 7, k = i & 127;
        float v = W[k * HID + n];
        __nv_bfloat16 hi = __float2bfloat16_rn(v);
        bh[n * 128 + k] = hi;
        bl[n * 128 + k] = __float2bfloat16_rn(v - __bfloat162float(hi));
    }
}

// ---------------- HMMA GEMM: 64(M) x 128(N) tile, 2 CTAs/SM ----------------
#define APAD 136
#define AT_BYTES (64 * APAD * 2)         // 17408
#define BT_BYTES (128 * APAD * 2)        // 34816
#define SM_AH 0
#define SM_AL AT_BYTES
#define SM_BH (2 * AT_BYTES)
#define SM_BL (2 * AT_BYTES + BT_BYTES)
#define SM_SC (2 * AT_BYTES + 2 * BT_BYTES)   // 104448
#define SM_SH (SM_SC + 512)
#define TC_SMEM (SM_SC + 1024)               // 105472 -> 2 CTAs/SM

template <int PRE>
__global__ void __launch_bounds__(256, 2)
mma_gemm_kernel(const float* __restrict__ A, int widx, const float* __restrict__ bias,
                float* __restrict__ C, int M, int slot,
                const float* __restrict__ gamma, const float* __restrict__ beta,
                int oslot) {
    extern __shared__ unsigned char smem[];
    int tid = threadIdx.x, lane = tid & 31, wid = tid >> 5;
    int m0 = blockIdx.x * 64;
    uint32_t sb = smem_u32(smem);
    float* sScale = (float*)(smem + SM_SC);
    float* sShift = (float*)(smem + SM_SH);

    if (PRE) {
        finalize_to_smem(slot, gamma, beta, sScale, sShift, tid);
        __syncthreads();
    }

    // ---- B: copy pre-split B^T (hi+lo) with row padding ----
    {
        const uint4* srcH = (const uint4*)(g_wsplit[widx]);
        const uint4* srcL = (const uint4*)(g_wsplit[widx] + 32768);
#pragma unroll
        for (int it = 0; it < 8; it++) {
            int i = tid + it * 256;
            int n = i >> 4, s = i & 15;
            *(uint4*)(smem + SM_BH + n * (APAD * 2) + s * 16) = __ldg(srcH + i);
            *(uint4*)(smem + SM_BL + n * (APAD * 2) + s * 16) = __ldg(srcL + i);
        }
    }

    // ---- A: load (4 threads/row), optional BN+GELU, split hi/lo ----
    {
        int r = tid >> 2, qt = tid & 3;
        bool valid = (m0 + r) < M;
        const float4* Arow = (const float4*)(A + (size_t)(m0 + r) * HID + qt * 32);
#pragma unroll
        for (int jj = 0; jj < 8; jj++) {
            int col = qt * 32 + jj * 4;
            float4 v = valid ? __ldg(Arow + jj) : make_float4(0.f, 0.f, 0.f, 0.f);
            if (PRE) {
                float4 sc = ((const float4*)sScale)[col >> 2];
                float4 sh = ((const float4*)sShift)[col >> 2];
                v.x = gelu_exact(v.x * sc.x + sh.x);
                v.y = gelu_exact(v.y * sc.y + sh.y);
                v.z = gelu_exact(v.z * sc.z + sh.z);
                v.w = gelu_exact(v.w * sc.w + sh.w);
            }
            __nv_bfloat16 h0 = __float2bfloat16_rn(v.x), h1 = __float2bfloat16_rn(v.y);
            __nv_bfloat16 h2 = __float2bfloat16_rn(v.z), h3 = __float2bfloat16_rn(v.w);
            float l0 = v.x - __bfloat162float(h0), l1 = v.y - __bfloat162float(h1);
            float l2 = v.z - __bfloat162float(h2), l3 = v.w - __bfloat162float(h3);
            uint2 hp, lp;
            hp.x = (uint32_t)__bfloat16_as_ushort(h0) | ((uint32_t)__bfloat16_as_ushort(h1) << 16);
            hp.y = (uint32_t)__bfloat16_as_ushort(h2) | ((uint32_t)__bfloat16_as_ushort(h3) << 16);
            lp.x = (uint32_t)__bfloat16_as_ushort(__float2bfloat16_rn(l0)) |
                   ((uint32_t)__bfloat16_as_ushort(__float2bfloat16_rn(l1)) << 16);
            lp.y = (uint32_t)__bfloat16_as_ushort(__float2bfloat16_rn(l2)) |
                   ((uint32_t)__bfloat16_as_ushort(__float2bfloat16_rn(l3)) << 16);
            uint32_t off = r * (APAD * 2) + col * 2;
            *(uint2*)(smem + SM_AH + off) = hp;
            *(uint2*)(smem + SM_AL + off) = lp;
        }
    }
    __syncthreads();

    // ---- MMA mainloop: warp grid 2(M) x 4(N), warp tile 32x32 ----
    int wm = wid & 1, wn = wid >> 1;
    int mbase = wm * 32, nbase = wn * 32;
    float acc[2][4][4];
#pragma unroll
    for (int i = 0; i < 2; i++)
#pragma unroll
        for (int j = 0; j < 4; j++)
#pragma unroll
            for (int c = 0; c < 4; c++) acc[i][j][c] = 0.f;

    int q = lane >> 3, riq = lane & 7;
#pragma unroll
    for (int ks = 0; ks < 8; ks++) {
        uint32_t ah[2][4], al[2][4], bh[4][2], bl[4][2];
#pragma unroll
        for (int i = 0; i < 2; i++) {
            int row = mbase + i * 16 + (q & 1) * 8 + riq;
            int kb = ks * 16 + (q >> 1) * 8;
            uint32_t addr = sb + SM_AH + row * (APAD * 2) + kb * 2;
            LDMATRIX_X4(ah[i], addr);
            LDMATRIX_X4(al[i], addr + AT_BYTES);
        }
#pragma unroll
        for (int j = 0; j < 2; j++) {
            int n = nbase + j * 16 + (q >> 1) * 8 + riq;
            int kb = ks * 16 + (q & 1) * 8;
            uint32_t addr = sb + SM_BH + n * (APAD * 2) + kb * 2;
            uint32_t t4[4];
            LDMATRIX_X4(t4, addr);
            bh[j * 2][0] = t4[0]; bh[j * 2][1] = t4[1];
            bh[j * 2 + 1][0] = t4[2]; bh[j * 2 + 1][1] = t4[3];
            LDMATRIX_X4(t4, addr + BT_BYTES);
            bl[j * 2][0] = t4[0]; bl[j * 2][1] = t4[1];
            bl[j * 2 + 1][0] = t4[2]; bl[j * 2 + 1][1] = t4[3];
        }
#pragma unroll
        for (int i = 0; i < 2; i++)
#pragma unroll
            for (int j = 0; j < 4; j++) {
                MMA16816(acc[i][j], ah[i], bh[j]);
                MMA16816(acc[i][j], ah[i], bl[j]);
                MMA16816(acc[i][j], al[i], bh[j]);
            }
    }
    __syncthreads();   // tiles consumed; reuse smem for C staging

    // ---- epilogue: regs -> smem (+bias) -> coalesced STG + fused stats ----
    float* sC = (float*)smem;   // 64 x 132 floats = 33792 B (fits in Ah+Al)
    int g = lane >> 2, tc = (lane & 3) * 2;
#pragma unroll
    for (int i = 0; i < 2; i++) {
        int row0 = mbase + i * 16 + g;
#pragma unroll
        for (int j = 0; j < 4; j++) {
            int col = nbase + j * 8 + tc;
            float b0 = __ldg(&bias[col]), b1 = __ldg(&bias[col + 1]);
            sC[row0 * 132 + col]           = acc[i][j][0] + b0;
            sC[row0 * 132 + col + 1]       = acc[i][j][1] + b1;
            sC[(row0 + 8) * 132 + col]     = acc[i][j][2] + b0;
            sC[(row0 + 8) * 132 + col + 1] = acc[i][j][3] + b1;
        }
    }
    __syncthreads();

    {
        int r2 = tid >> 2, qt = tid & 3;
        if (m0 + r2 < M) {
            float4* dst = (float4*)(C + (size_t)(m0 + r2) * HID + qt * 32);
            const float4* src = (const float4*)(sC + r2 * 132 + qt * 32);
#pragma unroll
            for (int i = 0; i < 8; i++) dst[i] = src[i];
        }
    }

    {
        int nrows = min(64, M - m0);
        int c = tid & 127;
        int rbeg = (tid >> 7) * 32;
        int rend = min(rbeg + 32, nrows);
        float s = 0.f, s2 = 0.f;
        for (int rr = rbeg; rr < rend; rr++) {
            float v = sC[rr * 132 + c];
            s += v; s2 += v * v;
        }
        atomicAdd(&g_sum[oslot * HID + c], s);
        atomicAdd(&g_sumsq[oslot * HID + c], s2);
    }
}

// ---------------- JumpingKnowledge attention ----------------
__global__ void jk_kernel(const float* __restrict__ att) {
    int gw = (blockIdx.x * blockDim.x + threadIdx.x) >> 5;
    int lane = threadIdx.x & 31;
    if (gw >= N_NODES) return;
    float v[NL][4];
    float s[NL];
#pragma unroll
    for (int l = 0; l < NL; l++) {
        float d = 0.f;
#pragma unroll
        for (int j = 0; j < 4; j++) {
            int c = lane + 32 * j;
            v[l][j] = g_hs[l][gw * HID + c];
            d += v[l][j] * __ldg(&att[l * HID + c]);
        }
        s[l] = d;
    }
#pragma unroll
    for (int off = 16; off; off >>= 1) {
#pragma unroll
        for (int l = 0; l < NL; l++) s[l] += __shfl_xor_sync(0xffffffffu, s[l], off);
    }
    float m = fmaxf(fmaxf(s[0], s[1]), fmaxf(s[2], s[3]));
    float e[NL], tot = 0.f;
#pragma unroll
    for (int l = 0; l < NL; l++) { e[l] = expf((s[l] - m) * (1.0f / HID)); tot += e[l]; }
    float inv = 1.0f / tot;
#pragma unroll
    for (int j = 0; j < 4; j++) {
        float o = 0.f;
#pragma unroll
        for (int l = 0; l < NL; l++) o += e[l] * v[l][j];
        g_x[gw * HID + lane + 32 * j] = o * inv;
    }
}

// ---------------- pooling ----------------
#define POOL_BLOCKS 500
__global__ void pool_scan_kernel(const int* __restrict__ batch) {
    const int CH = (N_NODES + POOL_BLOCKS - 1) / POOL_BLOCKS;   // 100
    int c = threadIdx.x;
    int n0 = blockIdx.x * CH;
    int n1 = min(n0 + CH, N_NODES);
    if (n0 >= n1) return;
    int g = batch[n0];
    float s = 0.f, mx = -FLT_MAX;
    int cnt = 0;
    for (int n = n0; n < n1; ++n) {
        int gn = batch[n];
        if (gn != g) {
            atomicAdd(&g_psum[g * HID + c], s);
            atomicMaxF(&g_pmax[g * HID + c], mx);
            if (c == 0) atomicAdd(&g_pcnt[g], cnt);
            g = gn; s = 0.f; mx = -FLT_MAX; cnt = 0;
        }
        float v = g_x[n * HID + c];
        s += v; mx = fmaxf(mx, v); cnt++;
    }
    atomicAdd(&g_psum[g * HID + c], s);
    atomicMaxF(&g_pmax[g * HID + c], mx);
    if (c == 0) atomicAdd(&g_pcnt[g], cnt);
}

// ---------------- head ----------------
__global__ void head_kernel(const float* __restrict__ pwraw,
                            const float* __restrict__ fcA_w, const float* __restrict__ fcA_b,
                            const float* __restrict__ ln_g, const float* __restrict__ ln_b,
                            const float* __restrict__ fcB_w, const float* __restrict__ fcB_b,
                            float* __restrict__ out) {
    __shared__ float sp[HID];
    __shared__ float sh[HID];
    __shared__ float red[HID];
    int g = blockIdx.x, c = threadIdx.x;

    float w0 = pwraw[0], w1 = pwraw[1], w2 = pwraw[2];
    float mw = fmaxf(w0, fmaxf(w1, w2));
    float e0 = expf(w0 - mw), e1 = expf(w1 - mw), e2 = expf(w2 - mw);
    float et = 1.0f / (e0 + e1 + e2);
    float pw0 = e0 * et, pw1 = e1 * et, pw2 = e2 * et;

    float cnt = (float)g_pcnt[g];
    float s = g_psum[g * HID + c];
    float mean = s / fmaxf(cnt, 1.0f);
    float mx = (cnt > 0.f) ? g_pmax[g * HID + c] : 0.0f;
    float pooled = s * pw0 + mean * pw1 + mx * pw2;
    sp[c] = pooled;
    __syncthreads();

    float acc = fcA_b[c];
#pragma unroll 8
    for (int k = 0; k < HID; k++) acc += sp[k] * fcA_w[k * HID + c];

    red[c] = acc;
    __syncthreads();
    for (int st = 64; st > 0; st >>= 1) { if (c < st) red[c] += red[c + st]; __syncthreads(); }
    float mu = red[0] * (1.0f / HID);
    __syncthreads();
    float d = acc - mu;
    red[c] = d * d;
    __syncthreads();
    for (int st = 64; st > 0; st >>= 1) { if (c < st) red[c] += red[c + st]; __syncthreads(); }
    float var = red[0] * (1.0f / HID);
    float y = d * rsqrtf(var + 1e-5f) * ln_g[c] + ln_b[c];
    float h = gelu_exact(y) + pooled;
    sh[c] = h;
    __syncthreads();

    if (c < LAT) {
        float o = fcB_b[c];
#pragma unroll 8
        for (int k = 0; k < HID; k++) o += sh[k] * fcB_w[k * LAT + c];
        out[g * LAT + c] = o;
    }
}

// ---------------- launcher ----------------
extern "C" void kernel_launch(void* const* d_in, const int* in_sizes, int n_in,
                              void* d_out, int out_size) {
    const float* x      = (const float*)d_in[0];
    const int*   ei     = (const int*)d_in[1];
    const int*   batch  = (const int*)d_in[2];
    const float* ibn_g  = (const float*)d_in[3];
    const float* ibn_b  = (const float*)d_in[4];
    const float* eps    = (const float*)d_in[5];
    const float* fc1_w  = (const float*)d_in[6];
    const float* fc1_b  = (const float*)d_in[7];
    const float* bn1_g  = (const float*)d_in[8];
    const float* bn1_b  = (const float*)d_in[9];
    const float* fc2_w  = (const float*)d_in[10];
    const float* fc2_b  = (const float*)d_in[11];
    const float* bn_g   = (const float*)d_in[12];
    const float* bn_b   = (const float*)d_in[13];
    const float* att_w  = (const float*)d_in[14];
    const float* pool_w = (const float*)d_in[15];
    const float* fcA_w  = (const float*)d_in[16];
    const float* fcA_b  = (const float*)d_in[17];
    const float* ln_g   = (const float*)d_in[18];
    const float* ln_b   = (const float*)d_in[19];
    const float* fcB_w  = (const float*)d_in[20];
    const float* fcB_b  = (const float*)d_in[21];
    float* out = (float*)d_out;

    const int* srcp = ei;
    const int* dstp = ei + N_EDGES;

    cudaFuncSetAttribute(mma_gemm_kernel<0>, cudaFuncAttributeMaxDynamicSharedMemorySize, TC_SMEM);
    cudaFuncSetAttribute(mma_gemm_kernel<1>, cudaFuncAttributeMaxDynamicSharedMemorySize, TC_SMEM);

    float *p_x, *p_h, *p_t, *p_hs;
    cudaGetSymbolAddress((void**)&p_x, g_x);
    cudaGetSymbolAddress((void**)&p_h, g_h);
    cudaGetSymbolAddress((void**)&p_t, g_t);
    cudaGetSymbolAddress((void**)&p_hs, g_hs);

    const int GEMM_GRID = (N_NODES + 63) / 64;          // 782
    const int EW_GRID   = (N_NODES * HID) / (256 * 4);  // 6250
    const int SCAN_GRID = (N_NODES + 1023) / 1024;      // 49
    const int INIT_GRID = (N_GRAPHS * HID + 255) / 256; // 256 -> covers 65536 (the R6 fix)

    zero_init_kernel<<<INIT_GRID, 256>>>();
    wsplit_kernel<<<64, 256>>>(fc1_w, fc2_w);
    colstats_kernel<<<256, 128>>>(x, N_NODES, 0);
    bn_apply_kernel<false><<<EW_GRID, 256>>>(x, p_x, 0, ibn_g, ibn_b);

    hist_kernel<<<(N_EDGES + 511) / 512, 512>>>(dstp);
    scan1_kernel<<<SCAN_GRID, 1024>>>();
    scan2_kernel<<<1, 64>>>(SCAN_GRID);
    scan3_kernel<<<SCAN_GRID, 1024>>>();
    scatter_kernel<<<(N_EDGES + 511) / 512, 512>>>(srcp, dstp);

    for (int l = 0; l < NL; l++) {
        int s1 = 1 + 2 * l, s2 = 2 + 2 * l;
        agg_kernel<<<N_NODES, 128>>>(l, eps);
        mma_gemm_kernel<0><<<GEMM_GRID, 256, TC_SMEM>>>(p_h, l * 2 + 0, fc1_b + l * HID,
                                                        p_t, N_NODES, 0, nullptr, nullptr, s1);
        mma_gemm_kernel<1><<<GEMM_GRID, 256, TC_SMEM>>>(p_t, l * 2 + 1, fc2_b + l * HID,
                                                        p_t, N_NODES, s1,
                                                        bn1_g + l * HID, bn1_b + l * HID, s2);
        bn_apply_kernel<true><<<EW_GRID, 256>>>(p_t, p_hs + (size_t)l * N_NODES * HID,
                                                s2, bn_g + l * HID, bn_b + l * HID);
    }

    jk_kernel<<<(N_NODES * 32) / 256, 256>>>(att_w);
    pool_scan_kernel<<<POOL_BLOCKS, 128>>>(batch);
    head_kernel<<<N_GRAPHS, 128>>>(pool_w, fcA_w, fcA_b, ln_g, ln_b, fcB_w, fcB_b, out);
}